// round 14
// baseline (speedup 1.0000x reference)
#include <cuda_runtime.h>

#define N_SAMPLES 2048
#define XDIM      768
#define LOWER     40

// h-GEMM tiling
#define MT     64                    // rows per block
#define KC     48                    // k per smem chunk
#define KPAD   52                    // stride: %4==0 (float4) and conflict-free
#define SPLIT  4
#define KSEG   (XDIM / SPLIT)        // 192
#define NCHUNK (KSEG / KC)           // 4

// pairwise tiling
#define JT  64                       // j per block (smem tile)
#define IB  256                      // i per block (1 per thread)
#define NJB (N_SAMPLES / JT)         // 32
#define NIB (N_SAMPLES / IB)         // 8
#define NPAIR (NJB * NIB)            // 256

__device__ float g_hx[SPLIT][N_SAMPLES * LOWER];
__device__ float g_hy[SPLIT][N_SAMPLES * LOWER];
__device__ float g_part_exp[NPAIR];
__device__ float g_part_t0[NPAIR];
__device__ unsigned g_count;          // zero-initialized; reset by last block

// ---- packed fp32x2 helpers ----
typedef unsigned long long u64p;
__device__ __forceinline__ u64p pk2(float lo, float hi) {
    u64p r; asm("mov.b64 %0, {%1, %2};" : "=l"(r) : "f"(lo), "f"(hi)); return r;
}
__device__ __forceinline__ void upk2(u64p v, float& lo, float& hi) {
    asm("mov.b64 {%0, %1}, %2;" : "=f"(lo), "=f"(hi) : "l"(v));
}
__device__ __forceinline__ u64p add2(u64p a, u64p b) {
    u64p r; asm("add.rn.f32x2 %0, %1, %2;" : "=l"(r) : "l"(a), "l"(b)); return r;
}
__device__ __forceinline__ u64p fma2(u64p a, u64p b, u64p c) {
    u64p r; asm("fma.rn.f32x2 %0, %1, %2, %3;" : "=l"(r) : "l"(a), "l"(b), "l"(c)); return r;
}
__device__ __forceinline__ u64p relu2(u64p v) {
    float lo, hi; upk2(v, lo, hi);
    return pk2(fmaxf(lo, 0.f), fmaxf(hi, 0.f));
}

// ---------------------------------------------------------------------------
// Kernel A: partial GEMMs, double-buffered smem, 2 rows x 5 units per thread.
// grid = (32, 2, 4): x = row tile, y = x/y side, z = K quarter. block = 256.
// ---------------------------------------------------------------------------
__global__ __launch_bounds__(256, 2) void h_gemm(const float* __restrict__ Xin,
                                                 const float* __restrict__ Yin,
                                                 const float* __restrict__ W1) {
    __shared__ float xs[2][MT][KPAD];       // 2 x 13.3 KB
    __shared__ float ws[2][LOWER][KPAD];    // 2 x 8.3 KB   (total 43.3 KB)

    const float* X = blockIdx.y ? Yin : Xin;
    float* H = blockIdx.y ? g_hy[blockIdx.z] : g_hx[blockIdx.z];
    const int coloff = (blockIdx.y ? XDIM : 0) + blockIdx.z * KSEG;
    const int kbase  = blockIdx.z * KSEG;

    const int tid  = threadIdx.x;
    const int row0 = blockIdx.x * MT;
    const int uu   = tid & 7;            // units [uu*5, uu*5+5)
    const int r0   = (tid >> 3) * 2;     // rows r0, r0+1

    // hoisted per-thread tile coordinates (loop-invariant across chunks)
    int xr[3], xk[3], wu[2], wk[2];
    #pragma unroll
    for (int q = 0; q < 3; q++) {
        int idx = tid + q * 256;
        xr[q] = idx / 12; xk[q] = (idx % 12) * 4;
    }
    #pragma unroll
    for (int q = 0; q < 2; q++) {
        int idx = tid + q * 256;
        wu[q] = idx / 12; wk[q] = (idx % 12) * 4;
    }

    u64p acc[2][5];
    #pragma unroll
    for (int r = 0; r < 2; r++)
        #pragma unroll
        for (int jj = 0; jj < 5; jj++) acc[r][jj] = 0ull;

    float4 rx[3], rw[2];

    auto ldg = [&](int c) {
        #pragma unroll
        for (int q = 0; q < 3; q++)
            rx[q] = *(const float4*)&X[(row0 + xr[q]) * XDIM + kbase + c * KC + xk[q]];
        #pragma unroll
        for (int q = 0; q < 2; q++)
            if (tid + q * 256 < 480)
                rw[q] = *(const float4*)&W1[wu[q] * (2 * XDIM) + coloff + c * KC + wk[q]];
    };
    auto sts = [&](int b) {
        #pragma unroll
        for (int q = 0; q < 3; q++)
            *(float4*)&xs[b][xr[q]][xk[q]] = rx[q];
        #pragma unroll
        for (int q = 0; q < 2; q++)
            if (tid + q * 256 < 480)
                *(float4*)&ws[b][wu[q]][wk[q]] = rw[q];
    };

    ldg(0); sts(0); __syncthreads();

    #pragma unroll
    for (int c = 0; c < NCHUNK; c++) {
        const int cur = c & 1;
        if (c + 1 < NCHUNK) ldg(c + 1);

        #pragma unroll
        for (int kk = 0; kk < KC; kk += 4) {
            ulonglong2 xv0 = *(const ulonglong2*)&xs[cur][r0][kk];
            ulonglong2 xv1 = *(const ulonglong2*)&xs[cur][r0 + 1][kk];
            #pragma unroll
            for (int jj = 0; jj < 5; jj++) {
                ulonglong2 wv = *(const ulonglong2*)&ws[cur][uu * 5 + jj][kk];
                acc[0][jj] = fma2(xv0.x, wv.x, acc[0][jj]);
                acc[0][jj] = fma2(xv0.y, wv.y, acc[0][jj]);
                acc[1][jj] = fma2(xv1.x, wv.x, acc[1][jj]);
                acc[1][jj] = fma2(xv1.y, wv.y, acc[1][jj]);
            }
        }

        if (c + 1 < NCHUNK) { sts(cur ^ 1); __syncthreads(); }
    }

    #pragma unroll
    for (int r = 0; r < 2; r++)
        #pragma unroll
        for (int jj = 0; jj < 5; jj++) {
            float lo, hi; upk2(acc[r][jj], lo, hi);
            H[(row0 + r0 + r) * LOWER + uu * 5 + jj] = lo + hi;
        }
}

// ---------------------------------------------------------------------------
// Kernel B: pairwise Sum exp(W2.relu(hy_i+b1+hx_j)+b2-1) + T0 diagonal,
// with in-kernel 4-way K-split merge and last-block final combine.
// grid = (32, 8), block = 256 (one i per thread).
// ---------------------------------------------------------------------------
__global__ __launch_bounds__(256, 2) void pair_kernel(const float* __restrict__ b1,
                                                      const float* __restrict__ W2,
                                                      const float* __restrict__ b2,
                                                      float* __restrict__ out) {
    __shared__ float hxs[JT * LOWER];   // 10 KB
    __shared__ float sred[32];
    __shared__ bool  is_last;

    const int tid  = threadIdx.x;
    const int lane = tid & 31;
    const int wid  = tid >> 5;
    const int i    = blockIdx.y * IB + tid;
    const int j0   = blockIdx.x * JT;
    const int bid  = blockIdx.y * NJB + blockIdx.x;
    const float b2v = b2[0];

    // a = sum_z hy_z[i] + b1 (packed), w = W2 (packed)
    u64p a_p[20], w_p[20];
    {
        const float4* h0 = (const float4*)&g_hy[0][i * LOWER];
        const float4* h1 = (const float4*)&g_hy[1][i * LOWER];
        const float4* h2 = (const float4*)&g_hy[2][i * LOWER];
        const float4* h3 = (const float4*)&g_hy[3][i * LOWER];
        #pragma unroll
        for (int q = 0; q < 10; q++) {
            float4 a = h0[q], b4 = h1[q], c = h2[q], d = h3[q];
            float4 bb = *(const float4*)&b1[4 * q];
            float4 w = *(const float4*)&W2[4 * q];
            a_p[2 * q]     = pk2(a.x + b4.x + c.x + d.x + bb.x,
                                 a.y + b4.y + c.y + d.y + bb.y);
            a_p[2 * q + 1] = pk2(a.z + b4.z + c.z + d.z + bb.z,
                                 a.w + b4.w + c.w + d.w + bb.w);
            w_p[2 * q]     = pk2(w.x, w.y);
            w_p[2 * q + 1] = pk2(w.z, w.w);
        }
    }

    // cooperative j-tile load, merging the 4 K-split partials. 640 float4.
    {
        const float4* A4 = (const float4*)&g_hx[0][j0 * LOWER];
        const float4* B4 = (const float4*)&g_hx[1][j0 * LOWER];
        const float4* C4 = (const float4*)&g_hx[2][j0 * LOWER];
        const float4* D4 = (const float4*)&g_hx[3][j0 * LOWER];
        float4* dst = (float4*)hxs;
        #pragma unroll
        for (int q = 0; q < 3; q++) {
            int idx = tid + 256 * q;
            if (idx < JT * LOWER / 4) {
                float4 a = A4[idx], b = B4[idx], c = C4[idx], d = D4[idx];
                float4 r;
                r.x = a.x + b.x + c.x + d.x;
                r.y = a.y + b.y + c.y + d.y;
                r.z = a.z + b.z + c.z + d.z;
                r.w = a.w + b.w + c.w + d.w;
                dst[idx] = r;
            }
        }
    }
    __syncthreads();

    const float cm1 = b2v - 1.0f;
    float s = 0.f;

    #pragma unroll 2
    for (int j = 0; j < JT; j++) {
        const ulonglong2* hj = (const ulonglong2*)&hxs[j * LOWER];  // 160B: aligned
        u64p acc0 = 0ull, acc1 = 0ull;
        #pragma unroll
        for (int q = 0; q < 10; q++) {
            ulonglong2 hv = hj[q];
            u64p t0 = relu2(add2(a_p[2 * q],     hv.x));
            u64p t1 = relu2(add2(a_p[2 * q + 1], hv.y));
            acc0 = fma2(t0, w_p[2 * q],     acc0);
            acc1 = fma2(t1, w_p[2 * q + 1], acc1);
        }
        float al, ah, bl, bh;
        upk2(acc0, al, ah); upk2(acc1, bl, bh);
        s += __expf((al + bl) + (ah + bh) + cm1);
    }

    // T0 diagonal: this block owns hx_i (merged) in smem iff i in its j-tile.
    float tdiag = 0.f;
    {
        int li = i - j0;
        if (li >= 0 && li < JT) {
            const ulonglong2* hi2 = (const ulonglong2*)&hxs[li * LOWER];
            u64p acc0 = 0ull, acc1 = 0ull;
            #pragma unroll
            for (int q = 0; q < 10; q++) {
                ulonglong2 hv = hi2[q];
                u64p t0 = relu2(add2(a_p[2 * q],     hv.x));
                u64p t1 = relu2(add2(a_p[2 * q + 1], hv.y));
                acc0 = fma2(t0, w_p[2 * q],     acc0);
                acc1 = fma2(t1, w_p[2 * q + 1], acc1);
            }
            float al, ah, bl, bh;
            upk2(acc0, al, ah); upk2(acc1, bl, bh);
            tdiag = (al + bl) + (ah + bh) + b2v;
        }
    }

    // block reduction (warp shuffles + one smem stage)
    #pragma unroll
    for (int off = 16; off; off >>= 1) {
        s     += __shfl_xor_sync(0xFFFFFFFFu, s,     off);
        tdiag += __shfl_xor_sync(0xFFFFFFFFu, tdiag, off);
    }
    if (lane == 0) { sred[wid] = s; sred[wid + 8] = tdiag; }
    __syncthreads();
    if (tid == 0) {
        float es = 0.f, ts = 0.f;
        #pragma unroll
        for (int w = 0; w < 8; w++) { es += sred[w]; ts += sred[w + 8]; }
        g_part_exp[bid] = es;
        g_part_t0 [bid] = ts;
        __threadfence();
        is_last = (atomicAdd(&g_count, 1u) == NPAIR - 1);
    }
    __syncthreads();

    // last block: combine all 256 partials and emit the scalar
    if (is_last) {
        __threadfence();
        float ex = g_part_exp[tid];
        float t0 = g_part_t0[tid];
        #pragma unroll
        for (int off = 16; off; off >>= 1) {
            ex += __shfl_xor_sync(0xFFFFFFFFu, ex, off);
            t0 += __shfl_xor_sync(0xFFFFFFFFu, t0, off);
        }
        if (lane == 0) { sred[wid] = ex; sred[wid + 8] = t0; }
        __syncthreads();
        if (tid == 0) {
            float exs = 0.f, t0s = 0.f;
            #pragma unroll
            for (int w = 0; w < 8; w++) { exs += sred[w]; t0s += sred[w + 8]; }
            out[0] = t0s / (float)N_SAMPLES
                   - exs / ((float)N_SAMPLES * (float)N_SAMPLES);
            g_count = 0;   // reset for next graph replay
        }
    }
}

// ---------------------------------------------------------------------------
extern "C" void kernel_launch(void* const* d_in, const int* in_sizes, int n_in,
                              void* d_out, int out_size) {
    (void)in_sizes; (void)n_in; (void)out_size;
    const float* x  = (const float*)d_in[0];
    const float* y  = (const float*)d_in[1];
    const float* W1 = (const float*)d_in[2];
    const float* b1 = (const float*)d_in[3];
    const float* W2 = (const float*)d_in[4];
    const float* b2 = (const float*)d_in[5];
    float* out = (float*)d_out;

    h_gemm<<<dim3(N_SAMPLES / MT, 2, SPLIT), 256>>>(x, y, W1);
    pair_kernel<<<dim3(NJB, NIB), 256>>>(b1, W2, b2, out);
}

// round 15
// speedup vs baseline: 1.0300x; 1.0300x over previous
#include <cuda_runtime.h>
#include <cuda_fp16.h>

#define N_SAMPLES 2048
#define XDIM      768
#define LOWER     40

// h-GEMM tiling
#define MT     64
#define KC     48
#define KPAD   52
#define SPLIT  4
#define KSEG   (XDIM / SPLIT)        // 192
#define NCHUNK (KSEG / KC)           // 4

// pairwise tiling
#define JT  64                       // j per block (smem tile)
#define IB  128                      // i per block (1 per thread)
#define NJB (N_SAMPLES / JT)         // 32
#define NIB (N_SAMPLES / IB)         // 16
#define NPAIR (NJB * NIB)            // 512

__device__ float g_hx[SPLIT][N_SAMPLES * LOWER];
__device__ float g_hy[SPLIT][N_SAMPLES * LOWER];
__device__ float g_part_exp[NPAIR];
__device__ float g_part_t0[NPAIR];
__device__ unsigned g_count;          // zero-init; reset by last block

// ---- packed fp32x2 helpers (h_gemm) ----
typedef unsigned long long u64p;
__device__ __forceinline__ void upk2(u64p v, float& lo, float& hi) {
    asm("mov.b64 {%0, %1}, %2;" : "=f"(lo), "=f"(hi) : "l"(v));
}
__device__ __forceinline__ u64p fma2(u64p a, u64p b, u64p c) {
    u64p r; asm("fma.rn.f32x2 %0, %1, %2, %3;" : "=l"(r) : "l"(a), "l"(b), "l"(c)); return r;
}

// ---------------------------------------------------------------------------
// Kernel A: partial GEMMs, double-buffered smem, 2 rows x 5 units per thread.
// grid = (32, 2, 4). block = 256.
// ---------------------------------------------------------------------------
__global__ __launch_bounds__(256, 2) void h_gemm(const float* __restrict__ Xin,
                                                 const float* __restrict__ Yin,
                                                 const float* __restrict__ W1) {
    __shared__ float xs[2][MT][KPAD];
    __shared__ float ws[2][LOWER][KPAD];

    const float* X = blockIdx.y ? Yin : Xin;
    float* H = blockIdx.y ? g_hy[blockIdx.z] : g_hx[blockIdx.z];
    const int coloff = (blockIdx.y ? XDIM : 0) + blockIdx.z * KSEG;
    const int kbase  = blockIdx.z * KSEG;

    const int tid  = threadIdx.x;
    const int row0 = blockIdx.x * MT;
    const int uu   = tid & 7;
    const int r0   = (tid >> 3) * 2;

    int xr[3], xk[3], wu[2], wk[2];
    #pragma unroll
    for (int q = 0; q < 3; q++) {
        int idx = tid + q * 256;
        xr[q] = idx / 12; xk[q] = (idx % 12) * 4;
    }
    #pragma unroll
    for (int q = 0; q < 2; q++) {
        int idx = tid + q * 256;
        wu[q] = idx / 12; wk[q] = (idx % 12) * 4;
    }

    u64p acc[2][5];
    #pragma unroll
    for (int r = 0; r < 2; r++)
        #pragma unroll
        for (int jj = 0; jj < 5; jj++) acc[r][jj] = 0ull;

    float4 rx[3], rw[2];

    auto ldg = [&](int c) {
        #pragma unroll
        for (int q = 0; q < 3; q++)
            rx[q] = *(const float4*)&X[(row0 + xr[q]) * XDIM + kbase + c * KC + xk[q]];
        #pragma unroll
        for (int q = 0; q < 2; q++)
            if (tid + q * 256 < 480)
                rw[q] = *(const float4*)&W1[wu[q] * (2 * XDIM) + coloff + c * KC + wk[q]];
    };
    auto sts = [&](int b) {
        #pragma unroll
        for (int q = 0; q < 3; q++)
            *(float4*)&xs[b][xr[q]][xk[q]] = rx[q];
        #pragma unroll
        for (int q = 0; q < 2; q++)
            if (tid + q * 256 < 480)
                *(float4*)&ws[b][wu[q]][wk[q]] = rw[q];
    };

    ldg(0); sts(0); __syncthreads();

    #pragma unroll
    for (int c = 0; c < NCHUNK; c++) {
        const int cur = c & 1;
        if (c + 1 < NCHUNK) ldg(c + 1);

        #pragma unroll
        for (int kk = 0; kk < KC; kk += 4) {
            ulonglong2 xv0 = *(const ulonglong2*)&xs[cur][r0][kk];
            ulonglong2 xv1 = *(const ulonglong2*)&xs[cur][r0 + 1][kk];
            #pragma unroll
            for (int jj = 0; jj < 5; jj++) {
                ulonglong2 wv = *(const ulonglong2*)&ws[cur][uu * 5 + jj][kk];
                acc[0][jj] = fma2(xv0.x, wv.x, acc[0][jj]);
                acc[0][jj] = fma2(xv0.y, wv.y, acc[0][jj]);
                acc[1][jj] = fma2(xv1.x, wv.x, acc[1][jj]);
                acc[1][jj] = fma2(xv1.y, wv.y, acc[1][jj]);
            }
        }

        if (c + 1 < NCHUNK) { sts(cur ^ 1); __syncthreads(); }
    }

    #pragma unroll
    for (int r = 0; r < 2; r++)
        #pragma unroll
        for (int jj = 0; jj < 5; jj++) {
            float lo, hi; upk2(acc[r][jj], lo, hi);
            H[(row0 + r0 + r) * LOWER + uu * 5 + jj] = lo + hi;
        }
}

// ---------------------------------------------------------------------------
// Kernel B: fp16 pairwise. grid = (32, 16) = 512 blocks, block = 128.
// Per thread: one i. j-tile (merged fp32 -> half) in smem, broadcast reads.
// ---------------------------------------------------------------------------
__global__ __launch_bounds__(128, 6) void pair_kernel(const float* __restrict__ b1,
                                                      const float* __restrict__ W2,
                                                      const float* __restrict__ b2,
                                                      float* __restrict__ out) {
    __shared__ __half hxs[JT * LOWER];   // 5 KB, row = 80 B (16B-aligned)
    __shared__ float sred[8];
    __shared__ bool  is_last;

    const int tid  = threadIdx.x;
    const int lane = tid & 31;
    const int wid  = tid >> 5;           // 0..3
    const int i    = blockIdx.y * IB + tid;
    const int j0   = blockIdx.x * JT;
    const int bid  = blockIdx.y * NJB + blockIdx.x;
    const float b2v = b2[0];

    // a = sum_z hy_z[i] + b1  ->  half2[20];  w = W2 -> half2[20]
    __half2 a_h[20], w_h[20];
    {
        const float4* h0 = (const float4*)&g_hy[0][i * LOWER];
        const float4* h1 = (const float4*)&g_hy[1][i * LOWER];
        const float4* h2 = (const float4*)&g_hy[2][i * LOWER];
        const float4* h3 = (const float4*)&g_hy[3][i * LOWER];
        #pragma unroll
        for (int q = 0; q < 10; q++) {
            float4 a = h0[q], b4 = h1[q], c = h2[q], d = h3[q];
            float4 bb = *(const float4*)&b1[4 * q];
            float4 w = *(const float4*)&W2[4 * q];
            a_h[2 * q]     = __floats2half2_rn(a.x + b4.x + c.x + d.x + bb.x,
                                               a.y + b4.y + c.y + d.y + bb.y);
            a_h[2 * q + 1] = __floats2half2_rn(a.z + b4.z + c.z + d.z + bb.z,
                                               a.w + b4.w + c.w + d.w + bb.w);
            w_h[2 * q]     = __floats2half2_rn(w.x, w.y);
            w_h[2 * q + 1] = __floats2half2_rn(w.z, w.w);
        }
    }

    // j-tile: merge 4 fp32 partials, convert to half. 640 float4 entries.
    {
        const float4* A4 = (const float4*)&g_hx[0][j0 * LOWER];
        const float4* B4 = (const float4*)&g_hx[1][j0 * LOWER];
        const float4* C4 = (const float4*)&g_hx[2][j0 * LOWER];
        const float4* D4 = (const float4*)&g_hx[3][j0 * LOWER];
        __half2* dst = (__half2*)hxs;
        #pragma unroll
        for (int q = 0; q < 5; q++) {
            int idx = tid + 128 * q;     // 0..639
            float4 a = A4[idx], b = B4[idx], c = C4[idx], d = D4[idx];
            dst[2 * idx]     = __floats2half2_rn(a.x + b.x + c.x + d.x,
                                                 a.y + b.y + c.y + d.y);
            dst[2 * idx + 1] = __floats2half2_rn(a.z + b.z + c.z + d.z,
                                                 a.w + b.w + c.w + d.w);
        }
    }
    __syncthreads();

    const float cm1 = b2v - 1.0f;
    const __half2 zero2 = __float2half2_rn(0.f);
    float s = 0.f;

    #pragma unroll 2
    for (int j = 0; j < JT; j++) {
        const uint4* hj = (const uint4*)&hxs[j * LOWER];   // 5 x 16B
        __half2 acc0 = zero2, acc1 = zero2, acc2 = zero2, acc3 = zero2;
        #pragma unroll
        for (int q = 0; q < 5; q++) {
            uint4 v = hj[q];
            __half2 h0 = *(__half2*)&v.x;
            __half2 h1 = *(__half2*)&v.y;
            __half2 h2 = *(__half2*)&v.z;
            __half2 h3 = *(__half2*)&v.w;
            acc0 = __hfma2(__hmax2(__hadd2(a_h[4 * q],     h0), zero2), w_h[4 * q],     acc0);
            acc1 = __hfma2(__hmax2(__hadd2(a_h[4 * q + 1], h1), zero2), w_h[4 * q + 1], acc1);
            acc2 = __hfma2(__hmax2(__hadd2(a_h[4 * q + 2], h2), zero2), w_h[4 * q + 2], acc2);
            acc3 = __hfma2(__hmax2(__hadd2(a_h[4 * q + 3], h3), zero2), w_h[4 * q + 3], acc3);
        }
        __half2 c = __hadd2(__hadd2(acc0, acc1), __hadd2(acc2, acc3));
        s += __expf(__low2float(c) + __high2float(c) + cm1);
    }

    // T0 diagonal: block owns hx_i in smem iff i is inside its j-tile.
    float tdiag = 0.f;
    {
        int li = i - j0;
        if (li >= 0 && li < JT) {
            const uint4* hi4 = (const uint4*)&hxs[li * LOWER];
            __half2 acc0 = zero2, acc1 = zero2, acc2 = zero2, acc3 = zero2;
            #pragma unroll
            for (int q = 0; q < 5; q++) {
                uint4 v = hi4[q];
                __half2 h0 = *(__half2*)&v.x;
                __half2 h1 = *(__half2*)&v.y;
                __half2 h2 = *(__half2*)&v.z;
                __half2 h3 = *(__half2*)&v.w;
                acc0 = __hfma2(__hmax2(__hadd2(a_h[4 * q],     h0), zero2), w_h[4 * q],     acc0);
                acc1 = __hfma2(__hmax2(__hadd2(a_h[4 * q + 1], h1), zero2), w_h[4 * q + 1], acc1);
                acc2 = __hfma2(__hmax2(__hadd2(a_h[4 * q + 2], h2), zero2), w_h[4 * q + 2], acc2);
                acc3 = __hfma2(__hmax2(__hadd2(a_h[4 * q + 3], h3), zero2), w_h[4 * q + 3], acc3);
            }
            __half2 c = __hadd2(__hadd2(acc0, acc1), __hadd2(acc2, acc3));
            tdiag = __low2float(c) + __high2float(c) + b2v;
        }
    }

    // block reduction: 4 warps
    #pragma unroll
    for (int off = 16; off; off >>= 1) {
        s     += __shfl_xor_sync(0xFFFFFFFFu, s,     off);
        tdiag += __shfl_xor_sync(0xFFFFFFFFu, tdiag, off);
    }
    if (lane == 0) { sred[wid] = s; sred[wid + 4] = tdiag; }
    __syncthreads();
    if (tid == 0) {
        float es = sred[0] + sred[1] + sred[2] + sred[3];
        float ts = sred[4] + sred[5] + sred[6] + sred[7];
        g_part_exp[bid] = es;
        g_part_t0 [bid] = ts;
        __threadfence();
        is_last = (atomicAdd(&g_count, 1u) == NPAIR - 1);
    }
    __syncthreads();

    // last block: combine 512 partials, emit scalar
    if (is_last) {
        __threadfence();
        float ex = 0.f, t0 = 0.f;
        #pragma unroll
        for (int k = 0; k < NPAIR / IB; k++) {
            ex += g_part_exp[tid + IB * k];
            t0 += g_part_t0 [tid + IB * k];
        }
        #pragma unroll
        for (int off = 16; off; off >>= 1) {
            ex += __shfl_xor_sync(0xFFFFFFFFu, ex, off);
            t0 += __shfl_xor_sync(0xFFFFFFFFu, t0, off);
        }
        if (lane == 0) { sred[wid] = ex; sred[wid + 4] = t0; }
        __syncthreads();
        if (tid == 0) {
            float exs = sred[0] + sred[1] + sred[2] + sred[3];
            float t0s = sred[4] + sred[5] + sred[6] + sred[7];
            out[0] = t0s / (float)N_SAMPLES
                   - exs / ((float)N_SAMPLES * (float)N_SAMPLES);
            g_count = 0;   // reset for next graph replay
        }
    }
}

// ---------------------------------------------------------------------------
extern "C" void kernel_launch(void* const* d_in, const int* in_sizes, int n_in,
                              void* d_out, int out_size) {
    (void)in_sizes; (void)n_in; (void)out_size;
    const float* x  = (const float*)d_in[0];
    const float* y  = (const float*)d_in[1];
    const float* W1 = (const float*)d_in[2];
    const float* b1 = (const float*)d_in[3];
    const float* W2 = (const float*)d_in[4];
    const float* b2 = (const float*)d_in[5];
    float* out = (float*)d_out;

    h_gemm<<<dim3(N_SAMPLES / MT, 2, SPLIT), 256>>>(x, y, W1);
    pair_kernel<<<dim3(NJB, NIB), 128>>>(b1, W2, b2, out);
}

// round 16
// speedup vs baseline: 1.0358x; 1.0056x over previous
#include <cuda_runtime.h>
#include <cuda_fp16.h>

#define N_SAMPLES 2048
#define XDIM      768
#define LOWER     40

// h-GEMM tiling
#define MT     64
#define KC     48
#define KPAD   52
#define SPLIT  4
#define KSEG   (XDIM / SPLIT)        // 192
#define NCHUNK (KSEG / KC)           // 4

// pairwise tiling
#define JT  32                       // j per block (smem tile)
#define IB  128                      // i per block (1 per thread)
#define NJB (N_SAMPLES / JT)         // 64
#define NIB (N_SAMPLES / IB)         // 16
#define NPAIR (NJB * NIB)            // 1024

__device__ float g_hx[SPLIT][N_SAMPLES * LOWER];
__device__ float g_hy[SPLIT][N_SAMPLES * LOWER];
__device__ float g_part_exp[NPAIR];
__device__ float g_part_t0[NPAIR];
__device__ unsigned g_count;          // zero-init; reset by last block

// ---- packed fp32x2 helpers (h_gemm) ----
typedef unsigned long long u64p;
__device__ __forceinline__ void upk2(u64p v, float& lo, float& hi) {
    asm("mov.b64 {%0, %1}, %2;" : "=f"(lo), "=f"(hi) : "l"(v));
}
__device__ __forceinline__ u64p fma2(u64p a, u64p b, u64p c) {
    u64p r; asm("fma.rn.f32x2 %0, %1, %2, %3;" : "=l"(r) : "l"(a), "l"(b), "l"(c)); return r;
}

// ---------------------------------------------------------------------------
// Kernel A: partial GEMMs, double-buffered smem, 2 rows x 5 units per thread.
// grid = (32, 2, 4). block = 256.
// ---------------------------------------------------------------------------
__global__ __launch_bounds__(256, 2) void h_gemm(const float* __restrict__ Xin,
                                                 const float* __restrict__ Yin,
                                                 const float* __restrict__ W1) {
    __shared__ float xs[2][MT][KPAD];
    __shared__ float ws[2][LOWER][KPAD];

    const float* X = blockIdx.y ? Yin : Xin;
    float* H = blockIdx.y ? g_hy[blockIdx.z] : g_hx[blockIdx.z];
    const int coloff = (blockIdx.y ? XDIM : 0) + blockIdx.z * KSEG;
    const int kbase  = blockIdx.z * KSEG;

    const int tid  = threadIdx.x;
    const int row0 = blockIdx.x * MT;
    const int uu   = tid & 7;
    const int r0   = (tid >> 3) * 2;

    int xr[3], xk[3], wu[2], wk[2];
    #pragma unroll
    for (int q = 0; q < 3; q++) {
        int idx = tid + q * 256;
        xr[q] = idx / 12; xk[q] = (idx % 12) * 4;
    }
    #pragma unroll
    for (int q = 0; q < 2; q++) {
        int idx = tid + q * 256;
        wu[q] = idx / 12; wk[q] = (idx % 12) * 4;
    }

    u64p acc[2][5];
    #pragma unroll
    for (int r = 0; r < 2; r++)
        #pragma unroll
        for (int jj = 0; jj < 5; jj++) acc[r][jj] = 0ull;

    float4 rx[3], rw[2];

    auto ldg = [&](int c) {
        #pragma unroll
        for (int q = 0; q < 3; q++)
            rx[q] = *(const float4*)&X[(row0 + xr[q]) * XDIM + kbase + c * KC + xk[q]];
        #pragma unroll
        for (int q = 0; q < 2; q++)
            if (tid + q * 256 < 480)
                rw[q] = *(const float4*)&W1[wu[q] * (2 * XDIM) + coloff + c * KC + wk[q]];
    };
    auto sts = [&](int b) {
        #pragma unroll
        for (int q = 0; q < 3; q++)
            *(float4*)&xs[b][xr[q]][xk[q]] = rx[q];
        #pragma unroll
        for (int q = 0; q < 2; q++)
            if (tid + q * 256 < 480)
                *(float4*)&ws[b][wu[q]][wk[q]] = rw[q];
    };

    ldg(0); sts(0); __syncthreads();

    #pragma unroll
    for (int c = 0; c < NCHUNK; c++) {
        const int cur = c & 1;
        if (c + 1 < NCHUNK) ldg(c + 1);

        #pragma unroll
        for (int kk = 0; kk < KC; kk += 4) {
            ulonglong2 xv0 = *(const ulonglong2*)&xs[cur][r0][kk];
            ulonglong2 xv1 = *(const ulonglong2*)&xs[cur][r0 + 1][kk];
            #pragma unroll
            for (int jj = 0; jj < 5; jj++) {
                ulonglong2 wv = *(const ulonglong2*)&ws[cur][uu * 5 + jj][kk];
                acc[0][jj] = fma2(xv0.x, wv.x, acc[0][jj]);
                acc[0][jj] = fma2(xv0.y, wv.y, acc[0][jj]);
                acc[1][jj] = fma2(xv1.x, wv.x, acc[1][jj]);
                acc[1][jj] = fma2(xv1.y, wv.y, acc[1][jj]);
            }
        }

        if (c + 1 < NCHUNK) { sts(cur ^ 1); __syncthreads(); }
    }

    #pragma unroll
    for (int r = 0; r < 2; r++)
        #pragma unroll
        for (int jj = 0; jj < 5; jj++) {
            float lo, hi; upk2(acc[r][jj], lo, hi);
            H[(row0 + r0 + r) * LOWER + uu * 5 + jj] = lo + hi;
        }
}

// ---------------------------------------------------------------------------
// Kernel B: fp16 pairwise. grid = (64, 16) = 1024 blocks, block = 128.
// Per thread: one i x 32 j. j-tile (merged fp32 -> half) in smem.
// ---------------------------------------------------------------------------
__global__ __launch_bounds__(128, 6) void pair_kernel(const float* __restrict__ b1,
                                                      const float* __restrict__ W2,
                                                      const float* __restrict__ b2,
                                                      float* __restrict__ out) {
    __shared__ __half hxs[JT * LOWER];   // 2.5 KB, row = 80 B (16B-aligned)
    __shared__ float sred[8];
    __shared__ bool  is_last;

    const int tid  = threadIdx.x;
    const int lane = tid & 31;
    const int wid  = tid >> 5;           // 0..3
    const int i    = blockIdx.y * IB + tid;
    const int j0   = blockIdx.x * JT;
    const int bid  = blockIdx.y * NJB + blockIdx.x;
    const float b2v = b2[0];

    // a = sum_z hy_z[i] + b1  ->  half2[20];  w = W2 -> half2[20]
    __half2 a_h[20], w_h[20];
    {
        const float4* h0 = (const float4*)&g_hy[0][i * LOWER];
        const float4* h1 = (const float4*)&g_hy[1][i * LOWER];
        const float4* h2 = (const float4*)&g_hy[2][i * LOWER];
        const float4* h3 = (const float4*)&g_hy[3][i * LOWER];
        #pragma unroll
        for (int q = 0; q < 10; q++) {
            float4 a = h0[q], b4 = h1[q], c = h2[q], d = h3[q];
            float4 bb = *(const float4*)&b1[4 * q];
            float4 w = *(const float4*)&W2[4 * q];
            a_h[2 * q]     = __floats2half2_rn(a.x + b4.x + c.x + d.x + bb.x,
                                               a.y + b4.y + c.y + d.y + bb.y);
            a_h[2 * q + 1] = __floats2half2_rn(a.z + b4.z + c.z + d.z + bb.z,
                                               a.w + b4.w + c.w + d.w + bb.w);
            w_h[2 * q]     = __floats2half2_rn(w.x, w.y);
            w_h[2 * q + 1] = __floats2half2_rn(w.z, w.w);
        }
    }

    // j-tile: merge 4 fp32 partials, convert to half. 320 float4 entries.
    {
        const float4* A4 = (const float4*)&g_hx[0][j0 * LOWER];
        const float4* B4 = (const float4*)&g_hx[1][j0 * LOWER];
        const float4* C4 = (const float4*)&g_hx[2][j0 * LOWER];
        const float4* D4 = (const float4*)&g_hx[3][j0 * LOWER];
        __half2* dst = (__half2*)hxs;
        #pragma unroll
        for (int q = 0; q < 3; q++) {
            int idx = tid + 128 * q;     // 0..383 (bound 320)
            if (idx < JT * LOWER / 4) {
                float4 a = A4[idx], b = B4[idx], c = C4[idx], d = D4[idx];
                dst[2 * idx]     = __floats2half2_rn(a.x + b.x + c.x + d.x,
                                                     a.y + b.y + c.y + d.y);
                dst[2 * idx + 1] = __floats2half2_rn(a.z + b.z + c.z + d.z,
                                                     a.w + b.w + c.w + d.w);
            }
        }
    }
    __syncthreads();

    const float cm1 = b2v - 1.0f;
    const __half2 zero2 = __float2half2_rn(0.f);
    float s = 0.f;

    #pragma unroll 2
    for (int j = 0; j < JT; j++) {
        const uint4* hj = (const uint4*)&hxs[j * LOWER];   // 5 x 16B
        __half2 acc0 = zero2, acc1 = zero2, acc2 = zero2, acc3 = zero2;
        #pragma unroll
        for (int q = 0; q < 5; q++) {
            uint4 v = hj[q];
            __half2 h0 = *(__half2*)&v.x;
            __half2 h1 = *(__half2*)&v.y;
            __half2 h2 = *(__half2*)&v.z;
            __half2 h3 = *(__half2*)&v.w;
            acc0 = __hfma2(__hmax2(__hadd2(a_h[4 * q],     h0), zero2), w_h[4 * q],     acc0);
            acc1 = __hfma2(__hmax2(__hadd2(a_h[4 * q + 1], h1), zero2), w_h[4 * q + 1], acc1);
            acc2 = __hfma2(__hmax2(__hadd2(a_h[4 * q + 2], h2), zero2), w_h[4 * q + 2], acc2);
            acc3 = __hfma2(__hmax2(__hadd2(a_h[4 * q + 3], h3), zero2), w_h[4 * q + 3], acc3);
        }
        __half2 c = __hadd2(__hadd2(acc0, acc1), __hadd2(acc2, acc3));
        s += __expf(__low2float(c) + __high2float(c) + cm1);
    }

    // T0 diagonal: block owns hx_i in smem iff i is inside its j-tile.
    float tdiag = 0.f;
    {
        int li = i - j0;
        if (li >= 0 && li < JT) {
            const uint4* hi4 = (const uint4*)&hxs[li * LOWER];
            __half2 acc0 = zero2, acc1 = zero2, acc2 = zero2, acc3 = zero2;
            #pragma unroll
            for (int q = 0; q < 5; q++) {
                uint4 v = hi4[q];
                __half2 h0 = *(__half2*)&v.x;
                __half2 h1 = *(__half2*)&v.y;
                __half2 h2 = *(__half2*)&v.z;
                __half2 h3 = *(__half2*)&v.w;
                acc0 = __hfma2(__hmax2(__hadd2(a_h[4 * q],     h0), zero2), w_h[4 * q],     acc0);
                acc1 = __hfma2(__hmax2(__hadd2(a_h[4 * q + 1], h1), zero2), w_h[4 * q + 1], acc1);
                acc2 = __hfma2(__hmax2(__hadd2(a_h[4 * q + 2], h2), zero2), w_h[4 * q + 2], acc2);
                acc3 = __hfma2(__hmax2(__hadd2(a_h[4 * q + 3], h3), zero2), w_h[4 * q + 3], acc3);
            }
            __half2 c = __hadd2(__hadd2(acc0, acc1), __hadd2(acc2, acc3));
            tdiag = __low2float(c) + __high2float(c) + b2v;
        }
    }

    // block reduction: 4 warps
    #pragma unroll
    for (int off = 16; off; off >>= 1) {
        s     += __shfl_xor_sync(0xFFFFFFFFu, s,     off);
        tdiag += __shfl_xor_sync(0xFFFFFFFFu, tdiag, off);
    }
    if (lane == 0) { sred[wid] = s; sred[wid + 4] = tdiag; }
    __syncthreads();
    if (tid == 0) {
        float es = sred[0] + sred[1] + sred[2] + sred[3];
        float ts = sred[4] + sred[5] + sred[6] + sred[7];
        g_part_exp[bid] = es;
        g_part_t0 [bid] = ts;
        __threadfence();
        is_last = (atomicAdd(&g_count, 1u) == NPAIR - 1);
    }
    __syncthreads();

    // last block: combine 1024 partials, emit scalar
    if (is_last) {
        __threadfence();
        float ex = 0.f, t0 = 0.f;
        #pragma unroll
        for (int k = 0; k < NPAIR / IB; k++) {
            ex += g_part_exp[tid + IB * k];
            t0 += g_part_t0 [tid + IB * k];
        }
        #pragma unroll
        for (int off = 16; off; off >>= 1) {
            ex += __shfl_xor_sync(0xFFFFFFFFu, ex, off);
            t0 += __shfl_xor_sync(0xFFFFFFFFu, t0, off);
        }
        if (lane == 0) { sred[wid] = ex; sred[wid + 4] = t0; }
        __syncthreads();
        if (tid == 0) {
            float exs = sred[0] + sred[1] + sred[2] + sred[3];
            float t0s = sred[4] + sred[5] + sred[6] + sred[7];
            out[0] = t0s / (float)N_SAMPLES
                   - exs / ((float)N_SAMPLES * (float)N_SAMPLES);
            g_count = 0;   // reset for next graph replay
        }
    }
}

// ---------------------------------------------------------------------------
extern "C" void kernel_launch(void* const* d_in, const int* in_sizes, int n_in,
                              void* d_out, int out_size) {
    (void)in_sizes; (void)n_in; (void)out_size;
    const float* x  = (const float*)d_in[0];
    const float* y  = (const float*)d_in[1];
    const float* W1 = (const float*)d_in[2];
    const float* b1 = (const float*)d_in[3];
    const float* W2 = (const float*)d_in[4];
    const float* b2 = (const float*)d_in[5];
    float* out = (float*)d_out;

    h_gemm<<<dim3(N_SAMPLES / MT, 2, SPLIT), 256>>>(x, y, W1);
    pair_kernel<<<dim3(NJB, NIB), 128>>>(b1, W2, b2, out);
}